// round 1
// baseline (speedup 1.0000x reference)
#include <cuda_runtime.h>
#include <math.h>

// Problem constants
#define BB 2
#define SS 2048
#define DD 1024
#define EE 1024
#define HH 16
#define DKK 64
#define E3 3072          // 3*E
#define NROWS (BB*SS)    // 4096

// Scratch (allocation-free rule: __device__ globals)
__device__ float g_qkv[(size_t)NROWS * E3];   // [B*S, 3E], e = h*192 + t*64 + dk
__device__ float g_attn[(size_t)NROWS * EE];  // [B*S, E],  e = h*64 + dk

// ---------------------------------------------------------------------------
// GEMM (NT): C[n][m] = sum_k A[n*K+k] * B[m*K+k] + bias[m]
// 64x64 tile, K-tile 16, 256 threads, 4x4 micro-tile per thread.
// ---------------------------------------------------------------------------
__global__ __launch_bounds__(256) void gemm_nt_kernel(
    const float* __restrict__ A, const float* __restrict__ B,
    const float* __restrict__ bias, float* __restrict__ C,
    int K, int M)
{
    __shared__ float As[16][68];  // [k][n-local]
    __shared__ float Bs[16][68];  // [k][m-local]

    const int tid = threadIdx.x;
    const int tx = tid & 15;
    const int ty = tid >> 4;
    const int n0 = blockIdx.y * 64;
    const int m0 = blockIdx.x * 64;

    const int lrow = tid >> 2;        // 0..63
    const int lk   = (tid & 3) * 4;   // 0,4,8,12

    const float* Ap = A + (size_t)(n0 + lrow) * K + lk;
    const float* Bp = B + (size_t)(m0 + lrow) * K + lk;

    float acc[4][4];
#pragma unroll
    for (int r = 0; r < 4; r++)
#pragma unroll
        for (int c = 0; c < 4; c++) acc[r][c] = 0.f;

    for (int k0 = 0; k0 < K; k0 += 16) {
        float4 va = *(const float4*)(Ap + k0);
        float4 vb = *(const float4*)(Bp + k0);
        As[lk+0][lrow] = va.x; As[lk+1][lrow] = va.y;
        As[lk+2][lrow] = va.z; As[lk+3][lrow] = va.w;
        Bs[lk+0][lrow] = vb.x; Bs[lk+1][lrow] = vb.y;
        Bs[lk+2][lrow] = vb.z; Bs[lk+3][lrow] = vb.w;
        __syncthreads();

#pragma unroll
        for (int k = 0; k < 16; k++) {
            float4 a = *(const float4*)&As[k][ty * 4];
            float4 b = *(const float4*)&Bs[k][tx * 4];
            float ar[4] = {a.x, a.y, a.z, a.w};
            float bc[4] = {b.x, b.y, b.z, b.w};
#pragma unroll
            for (int r = 0; r < 4; r++)
#pragma unroll
                for (int c = 0; c < 4; c++)
                    acc[r][c] = fmaf(ar[r], bc[c], acc[r][c]);
        }
        __syncthreads();
    }

    const float4 bs4 = *(const float4*)(bias + m0 + tx * 4);
    const float bb4[4] = {bs4.x, bs4.y, bs4.z, bs4.w};
#pragma unroll
    for (int r = 0; r < 4; r++) {
        int n = n0 + ty * 4 + r;
        float4 o;
        o.x = acc[r][0] + bb4[0];
        o.y = acc[r][1] + bb4[1];
        o.z = acc[r][2] + bb4[2];
        o.w = acc[r][3] + bb4[3];
        *(float4*)(C + (size_t)n * M + m0 + tx * 4) = o;
    }
}

// ---------------------------------------------------------------------------
// Flash attention, fp32. One block = 64 queries of one (b,h).
// 256 threads (16x16), 4x4 micro-tiles. Online softmax with running (m,l).
// Shared: Qs[q][dk], Ks[dk][kv] (transposed), Vs[kv][dk], Ps[q][kv].
// ---------------------------------------------------------------------------
#define ATTN_SMEM (4 * 64 * 68 * 4)

__global__ __launch_bounds__(256) void attn_kernel(
    const float* __restrict__ qkv, float* __restrict__ out)
{
    extern __shared__ float sm[];
    float (*Qs)[68] = (float(*)[68])(sm);
    float (*Ks)[68] = (float(*)[68])(sm + 1 * 64 * 68);
    float (*Vs)[68] = (float(*)[68])(sm + 2 * 64 * 68);
    float (*Ps)[68] = (float(*)[68])(sm + 3 * 64 * 68);

    const int tid = threadIdx.x;
    const int tx = tid & 15;
    const int ty = tid >> 4;
    const int b = blockIdx.z;
    const int h = blockIdx.y;
    const int q0 = blockIdx.x * 64;

    const int lrow = tid >> 2;        // 0..63
    const int lc   = (tid & 3) * 16;  // 0,16,32,48

    const float* base = qkv + (size_t)b * SS * E3 + h * (3 * DKK);

    // Load Q tile: Qs[q][dk]
    {
        const float* p = base + (size_t)(q0 + lrow) * E3 + lc;
#pragma unroll
        for (int f = 0; f < 4; f++) {
            float4 v = *(const float4*)(p + f * 4);
            *(float4*)&Qs[lrow][lc + f * 4] = v;
        }
    }

    float m[4], l[4], acc[4][4];
#pragma unroll
    for (int r = 0; r < 4; r++) {
        m[r] = -1e30f; l[r] = 0.f;
#pragma unroll
        for (int c = 0; c < 4; c++) acc[r][c] = 0.f;
    }
    const float scale = 0.125f;  // 1/sqrt(64)
    const int ty4 = ty * 4, tx4 = tx * 4;

    for (int kv0 = 0; kv0 < SS; kv0 += 64) {
        __syncthreads();  // previous PV/S reads done before overwriting Ks/Vs
        // Load K (transposed -> Ks[dk][kv]) and V (natural -> Vs[kv][dk])
        {
            const float* kp = base + (size_t)(kv0 + lrow) * E3 + DKK + lc;
            const float* vp = base + (size_t)(kv0 + lrow) * E3 + 2 * DKK + lc;
#pragma unroll
            for (int f = 0; f < 4; f++) {
                float4 kv4 = *(const float4*)(kp + f * 4);
                Ks[lc + f*4 + 0][lrow] = kv4.x;
                Ks[lc + f*4 + 1][lrow] = kv4.y;
                Ks[lc + f*4 + 2][lrow] = kv4.z;
                Ks[lc + f*4 + 3][lrow] = kv4.w;
                float4 vv4 = *(const float4*)(vp + f * 4);
                *(float4*)&Vs[lrow][lc + f * 4] = vv4;
            }
        }
        __syncthreads();

        // S = Q K^T * scale  (4x4 per thread)
        float s[4][4];
#pragma unroll
        for (int r = 0; r < 4; r++)
#pragma unroll
            for (int c = 0; c < 4; c++) s[r][c] = 0.f;

#pragma unroll 8
        for (int k = 0; k < 64; k++) {
            float ar[4];
#pragma unroll
            for (int r = 0; r < 4; r++) ar[r] = Qs[ty4 + r][k];
            float4 bv = *(const float4*)&Ks[k][tx4];
            float bc[4] = {bv.x, bv.y, bv.z, bv.w};
#pragma unroll
            for (int r = 0; r < 4; r++)
#pragma unroll
                for (int c = 0; c < 4; c++)
                    s[r][c] = fmaf(ar[r], bc[c], s[r][c]);
        }

        // Online softmax update, write P tile
#pragma unroll
        for (int r = 0; r < 4; r++) {
            float rm = -1e30f;
#pragma unroll
            for (int c = 0; c < 4; c++) {
                s[r][c] *= scale;
                rm = fmaxf(rm, s[r][c]);
            }
#pragma unroll
            for (int off = 8; off > 0; off >>= 1)
                rm = fmaxf(rm, __shfl_xor_sync(0xffffffffu, rm, off));
            float mn = fmaxf(m[r], rm);
            float alpha = __expf(m[r] - mn);
            float rs = 0.f;
#pragma unroll
            for (int c = 0; c < 4; c++) {
                float p = __expf(s[r][c] - mn);
                s[r][c] = p;
                rs += p;
            }
#pragma unroll
            for (int off = 8; off > 0; off >>= 1)
                rs += __shfl_xor_sync(0xffffffffu, rs, off);
            l[r] = l[r] * alpha + rs;
            m[r] = mn;
#pragma unroll
            for (int c = 0; c < 4; c++) acc[r][c] *= alpha;
            *(float4*)&Ps[ty4 + r][tx4] =
                make_float4(s[r][0], s[r][1], s[r][2], s[r][3]);
        }
        __syncthreads();

        // O += P V   (inner over kv j; Ps broadcast reads, Vs float4)
#pragma unroll 8
        for (int j = 0; j < 64; j++) {
            float ar[4];
#pragma unroll
            for (int r = 0; r < 4; r++) ar[r] = Ps[ty4 + r][j];
            float4 v = *(const float4*)&Vs[j][tx4];
            float vc[4] = {v.x, v.y, v.z, v.w};
#pragma unroll
            for (int r = 0; r < 4; r++)
#pragma unroll
                for (int c = 0; c < 4; c++)
                    acc[r][c] = fmaf(ar[r], vc[c], acc[r][c]);
        }
    }

    // Epilogue: out[b, q, h*64 + dk] = acc / l
    float* ob = out + (size_t)b * SS * EE + h * DKK;
#pragma unroll
    for (int r = 0; r < 4; r++) {
        float inv = 1.f / l[r];
        float4 o = make_float4(acc[r][0] * inv, acc[r][1] * inv,
                               acc[r][2] * inv, acc[r][3] * inv);
        *(float4*)(ob + (size_t)(q0 + ty4 + r) * EE + tx4) = o;
    }
}

// ---------------------------------------------------------------------------
extern "C" void kernel_launch(void* const* d_in, const int* in_sizes, int n_in,
                              void* d_out, int out_size)
{
    const float* x     = (const float*)d_in[0];  // [B,S,D]
    const float* W_qkv = (const float*)d_in[1];  // [3E, D]
    const float* b_qkv = (const float*)d_in[2];  // [3E]
    const float* W_o   = (const float*)d_in[3];  // [E, E]
    const float* b_o   = (const float*)d_in[4];  // [E]
    float* out = (float*)d_out;                  // [B,S,E]

    float *qkv_ptr, *attn_ptr;
    cudaGetSymbolAddress((void**)&qkv_ptr, g_qkv);
    cudaGetSymbolAddress((void**)&attn_ptr, g_attn);

    cudaFuncSetAttribute(attn_kernel,
                         cudaFuncAttributeMaxDynamicSharedMemorySize, ATTN_SMEM);

    // 1) QKV projection: [4096,1024] x [3072,1024]^T -> [4096,3072]
    gemm_nt_kernel<<<dim3(E3 / 64, NROWS / 64), 256>>>(
        x, W_qkv, b_qkv, qkv_ptr, DD, E3);

    // 2) Attention: grid (q-tiles, heads, batch)
    attn_kernel<<<dim3(SS / 64, HH, BB), 256, ATTN_SMEM>>>(qkv_ptr, attn_ptr);

    // 3) Output projection: [4096,1024] x [1024,1024]^T -> [4096,1024]
    gemm_nt_kernel<<<dim3(EE / 64, NROWS / 64), 256>>>(
        attn_ptr, W_o, b_o, out, EE, EE);
}

// round 2
// speedup vs baseline: 1.1284x; 1.1284x over previous
#include <cuda_runtime.h>
#include <math.h>
#include <stdint.h>

// Problem constants
#define BB 2
#define SS 2048
#define DD 1024
#define EE 1024
#define HH 16
#define DKK 64
#define E3 3072          // 3*E
#define NROWS (BB*SS)    // 4096

// Scratch (allocation-free rule: __device__ globals)
__device__ float g_qkv[(size_t)NROWS * E3];   // [B*S, 3E]
__device__ float g_attn[(size_t)NROWS * EE];  // [B*S, E]

// ---------------------------------------------------------------------------
// PTX helpers
// ---------------------------------------------------------------------------
__device__ __forceinline__ uint32_t smem_u32(const void* p) {
    return (uint32_t)__cvta_generic_to_shared(p);
}
__device__ __forceinline__ void cp_async16(uint32_t s, const void* g) {
    asm volatile("cp.async.cg.shared.global [%0], [%1], 16;\n" :: "r"(s), "l"(g));
}
__device__ __forceinline__ void cp_commit() {
    asm volatile("cp.async.commit_group;\n" ::: "memory");
}
template <int N>
__device__ __forceinline__ void cp_wait() {
    asm volatile("cp.async.wait_group %0;\n" :: "n"(N) : "memory");
}
__device__ __forceinline__ uint32_t cvt_tf32(float f) {
    uint32_t r;
    asm("cvt.rna.tf32.f32 %0, %1;" : "=r"(r) : "f"(f));
    return r;
}
__device__ __forceinline__ void mma_tf32(float* d, const uint32_t* a, const uint32_t* b) {
    asm volatile(
        "mma.sync.aligned.m16n8k8.row.col.f32.tf32.tf32.f32 "
        "{%0,%1,%2,%3}, {%4,%5,%6,%7}, {%8,%9}, {%0,%1,%2,%3};"
        : "+f"(d[0]), "+f"(d[1]), "+f"(d[2]), "+f"(d[3])
        : "r"(a[0]), "r"(a[1]), "r"(a[2]), "r"(a[3]), "r"(b[0]), "r"(b[1]));
}

// ---------------------------------------------------------------------------
// TF32 split GEMM (NT): C[n][m] = sum_k A[n][k]*B[m][k] + bias[m]
// Block 128x128, K-tile 32, 256 threads = 8 warps (2 row x 4 col),
// warp tile 64x32 = 4x4 m16n8k8 tiles. 3-pass split TF32 for fp32 accuracy.
// Smem row stride 36 floats -> conflict-free fragment loads.
// ---------------------------------------------------------------------------
#define BM 128
#define BN 128
#define BK 32
#define PAD 36
#define GEMM_SMEM (4 * BM * PAD * 4)   // 2 bufs x (A+B) = 73728 bytes

__global__ __launch_bounds__(256) void gemm_tf32_kernel(
    const float* __restrict__ A, const float* __restrict__ B,
    const float* __restrict__ bias, float* __restrict__ C,
    int K, int M)
{
    extern __shared__ float sm[];
    float* Abuf[2] = { sm, sm + BM * PAD };
    float* Bbuf[2] = { sm + 2 * BM * PAD, sm + 3 * BM * PAD };

    const int tid = threadIdx.x;
    const int lane = tid & 31;
    const int warp = tid >> 5;
    const int wr = warp >> 2;        // 0..1
    const int wc = warp & 3;         // 0..3
    const int g  = lane >> 2;        // 0..7
    const int tg = lane & 3;         // 0..3

    const int n0 = blockIdx.y * BM;
    const int m0 = blockIdx.x * BN;

    const int ldrow = tid >> 3;          // 0..31
    const int ldk   = (tid & 7) * 4;     // 0,4,...,28

    float acc[4][4][4];
#pragma unroll
    for (int mt = 0; mt < 4; mt++)
#pragma unroll
        for (int nt = 0; nt < 4; nt++)
#pragma unroll
            for (int i = 0; i < 4; i++) acc[mt][nt][i] = 0.f;

    const int KT = K / BK;

    // prologue: load tile 0 into buffer 0
    {
        float* as = Abuf[0]; float* bs = Bbuf[0];
#pragma unroll
        for (int p = 0; p < 4; p++) {
            int row = ldrow + p * 32;
            cp_async16(smem_u32(as + row * PAD + ldk),
                       A + (size_t)(n0 + row) * K + ldk);
            cp_async16(smem_u32(bs + row * PAD + ldk),
                       B + (size_t)(m0 + row) * K + ldk);
        }
        cp_commit();
    }

    for (int kt = 0; kt < KT; kt++) {
        if (kt + 1 < KT) {
            int nb = (kt + 1) & 1;
            int k0 = (kt + 1) * BK;
            float* as = Abuf[nb]; float* bs = Bbuf[nb];
#pragma unroll
            for (int p = 0; p < 4; p++) {
                int row = ldrow + p * 32;
                cp_async16(smem_u32(as + row * PAD + ldk),
                           A + (size_t)(n0 + row) * K + k0 + ldk);
                cp_async16(smem_u32(bs + row * PAD + ldk),
                           B + (size_t)(m0 + row) * K + k0 + ldk);
            }
        }
        cp_commit();
        cp_wait<1>();
        __syncthreads();

        const float* as = Abuf[kt & 1];
        const float* bs = Bbuf[kt & 1];

#pragma unroll
        for (int ks = 0; ks < 4; ks++) {
            const int kc = ks * 8 + tg;

            uint32_t ahi[4][4], alo[4][4];
#pragma unroll
            for (int mt = 0; mt < 4; mt++) {
                int r = wr * 64 + mt * 16 + g;
                float f0 = as[r * PAD + kc];
                float f1 = as[(r + 8) * PAD + kc];
                float f2 = as[r * PAD + kc + 4];
                float f3 = as[(r + 8) * PAD + kc + 4];
                ahi[mt][0] = cvt_tf32(f0);
                ahi[mt][1] = cvt_tf32(f1);
                ahi[mt][2] = cvt_tf32(f2);
                ahi[mt][3] = cvt_tf32(f3);
                alo[mt][0] = cvt_tf32(f0 - __uint_as_float(ahi[mt][0]));
                alo[mt][1] = cvt_tf32(f1 - __uint_as_float(ahi[mt][1]));
                alo[mt][2] = cvt_tf32(f2 - __uint_as_float(ahi[mt][2]));
                alo[mt][3] = cvt_tf32(f3 - __uint_as_float(ahi[mt][3]));
            }

            uint32_t bhi[4][2], blo[4][2];
#pragma unroll
            for (int nt = 0; nt < 4; nt++) {
                int m = wc * 32 + nt * 8 + g;
                float f0 = bs[m * PAD + kc];
                float f1 = bs[m * PAD + kc + 4];
                bhi[nt][0] = cvt_tf32(f0);
                bhi[nt][1] = cvt_tf32(f1);
                blo[nt][0] = cvt_tf32(f0 - __uint_as_float(bhi[nt][0]));
                blo[nt][1] = cvt_tf32(f1 - __uint_as_float(bhi[nt][1]));
            }

#pragma unroll
            for (int mt = 0; mt < 4; mt++)
#pragma unroll
                for (int nt = 0; nt < 4; nt++) {
                    mma_tf32(acc[mt][nt], ahi[mt], bhi[nt]);
                    mma_tf32(acc[mt][nt], alo[mt], bhi[nt]);
                    mma_tf32(acc[mt][nt], ahi[mt], blo[nt]);
                }
        }
        __syncthreads();
    }

    // epilogue with bias
#pragma unroll
    for (int mt = 0; mt < 4; mt++) {
        int row = n0 + wr * 64 + mt * 16 + g;
#pragma unroll
        for (int nt = 0; nt < 4; nt++) {
            int col = m0 + wc * 32 + nt * 8 + 2 * tg;
            float b0 = bias[col], b1 = bias[col + 1];
            float2 v0 = make_float2(acc[mt][nt][0] + b0, acc[mt][nt][1] + b1);
            float2 v1 = make_float2(acc[mt][nt][2] + b0, acc[mt][nt][3] + b1);
            *(float2*)(C + (size_t)row * M + col) = v0;
            *(float2*)(C + (size_t)(row + 8) * M + col) = v1;
        }
    }
}

// ---------------------------------------------------------------------------
// Flash attention, fp32 (unchanged from round 1). One block = 64 queries.
// ---------------------------------------------------------------------------
#define ATTN_SMEM (4 * 64 * 68 * 4)

__global__ __launch_bounds__(256) void attn_kernel(
    const float* __restrict__ qkv, float* __restrict__ out)
{
    extern __shared__ float smf[];
    float (*Qs)[68] = (float(*)[68])(smf);
    float (*Ks)[68] = (float(*)[68])(smf + 1 * 64 * 68);
    float (*Vs)[68] = (float(*)[68])(smf + 2 * 64 * 68);
    float (*Ps)[68] = (float(*)[68])(smf + 3 * 64 * 68);

    const int tid = threadIdx.x;
    const int tx = tid & 15;
    const int ty = tid >> 4;
    const int b = blockIdx.z;
    const int h = blockIdx.y;
    const int q0 = blockIdx.x * 64;

    const int lrow = tid >> 2;
    const int lc   = (tid & 3) * 16;

    const float* base = qkv + (size_t)b * SS * E3 + h * (3 * DKK);

    {
        const float* p = base + (size_t)(q0 + lrow) * E3 + lc;
#pragma unroll
        for (int f = 0; f < 4; f++) {
            float4 v = *(const float4*)(p + f * 4);
            *(float4*)&Qs[lrow][lc + f * 4] = v;
        }
    }

    float m[4], l[4], acc[4][4];
#pragma unroll
    for (int r = 0; r < 4; r++) {
        m[r] = -1e30f; l[r] = 0.f;
#pragma unroll
        for (int c = 0; c < 4; c++) acc[r][c] = 0.f;
    }
    const float scale = 0.125f;
    const int ty4 = ty * 4, tx4 = tx * 4;

    for (int kv0 = 0; kv0 < SS; kv0 += 64) {
        __syncthreads();
        {
            const float* kp = base + (size_t)(kv0 + lrow) * E3 + DKK + lc;
            const float* vp = base + (size_t)(kv0 + lrow) * E3 + 2 * DKK + lc;
#pragma unroll
            for (int f = 0; f < 4; f++) {
                float4 kv4 = *(const float4*)(kp + f * 4);
                Ks[lc + f*4 + 0][lrow] = kv4.x;
                Ks[lc + f*4 + 1][lrow] = kv4.y;
                Ks[lc + f*4 + 2][lrow] = kv4.z;
                Ks[lc + f*4 + 3][lrow] = kv4.w;
                float4 vv4 = *(const float4*)(vp + f * 4);
                *(float4*)&Vs[lrow][lc + f * 4] = vv4;
            }
        }
        __syncthreads();

        float s[4][4];
#pragma unroll
        for (int r = 0; r < 4; r++)
#pragma unroll
            for (int c = 0; c < 4; c++) s[r][c] = 0.f;

#pragma unroll 8
        for (int k = 0; k < 64; k++) {
            float ar[4];
#pragma unroll
            for (int r = 0; r < 4; r++) ar[r] = Qs[ty4 + r][k];
            float4 bv = *(const float4*)&Ks[k][tx4];
            float bc[4] = {bv.x, bv.y, bv.z, bv.w};
#pragma unroll
            for (int r = 0; r < 4; r++)
#pragma unroll
                for (int c = 0; c < 4; c++)
                    s[r][c] = fmaf(ar[r], bc[c], s[r][c]);
        }

#pragma unroll
        for (int r = 0; r < 4; r++) {
            float rm = -1e30f;
#pragma unroll
            for (int c = 0; c < 4; c++) {
                s[r][c] *= scale;
                rm = fmaxf(rm, s[r][c]);
            }
#pragma unroll
            for (int off = 8; off > 0; off >>= 1)
                rm = fmaxf(rm, __shfl_xor_sync(0xffffffffu, rm, off));
            float mn = fmaxf(m[r], rm);
            float alpha = __expf(m[r] - mn);
            float rs = 0.f;
#pragma unroll
            for (int c = 0; c < 4; c++) {
                float p = __expf(s[r][c] - mn);
                s[r][c] = p;
                rs += p;
            }
#pragma unroll
            for (int off = 8; off > 0; off >>= 1)
                rs += __shfl_xor_sync(0xffffffffu, rs, off);
            l[r] = l[r] * alpha + rs;
            m[r] = mn;
#pragma unroll
            for (int c = 0; c < 4; c++) acc[r][c] *= alpha;
            *(float4*)&Ps[ty4 + r][tx4] =
                make_float4(s[r][0], s[r][1], s[r][2], s[r][3]);
        }
        __syncthreads();

#pragma unroll 8
        for (int j = 0; j < 64; j++) {
            float ar[4];
#pragma unroll
            for (int r = 0; r < 4; r++) ar[r] = Ps[ty4 + r][j];
            float4 v = *(const float4*)&Vs[j][tx4];
            float vc[4] = {v.x, v.y, v.z, v.w};
#pragma unroll
            for (int r = 0; r < 4; r++)
#pragma unroll
                for (int c = 0; c < 4; c++)
                    acc[r][c] = fmaf(ar[r], vc[c], acc[r][c]);
        }
    }

    float* ob = out + (size_t)b * SS * EE + h * DKK;
#pragma unroll
    for (int r = 0; r < 4; r++) {
        float inv = 1.f / l[r];
        float4 o = make_float4(acc[r][0] * inv, acc[r][1] * inv,
                               acc[r][2] * inv, acc[r][3] * inv);
        *(float4*)(ob + (size_t)(q0 + ty4 + r) * EE + tx4) = o;
    }
}

// ---------------------------------------------------------------------------
extern "C" void kernel_launch(void* const* d_in, const int* in_sizes, int n_in,
                              void* d_out, int out_size)
{
    const float* x     = (const float*)d_in[0];
    const float* W_qkv = (const float*)d_in[1];
    const float* b_qkv = (const float*)d_in[2];
    const float* W_o   = (const float*)d_in[3];
    const float* b_o   = (const float*)d_in[4];
    float* out = (float*)d_out;

    float *qkv_ptr, *attn_ptr;
    cudaGetSymbolAddress((void**)&qkv_ptr, g_qkv);
    cudaGetSymbolAddress((void**)&attn_ptr, g_attn);

    cudaFuncSetAttribute(gemm_tf32_kernel,
                         cudaFuncAttributeMaxDynamicSharedMemorySize, GEMM_SMEM);
    cudaFuncSetAttribute(attn_kernel,
                         cudaFuncAttributeMaxDynamicSharedMemorySize, ATTN_SMEM);

    // 1) QKV projection: [4096,1024] x [3072,1024]^T -> [4096,3072]
    gemm_tf32_kernel<<<dim3(E3 / BN, NROWS / BM), 256, GEMM_SMEM>>>(
        x, W_qkv, b_qkv, qkv_ptr, DD, E3);

    // 2) Attention
    attn_kernel<<<dim3(SS / 64, HH, BB), 256, ATTN_SMEM>>>(qkv_ptr, attn_ptr);

    // 3) Output projection: [4096,1024] x [1024,1024]^T -> [4096,1024]
    gemm_tf32_kernel<<<dim3(EE / BN, NROWS / BM), 256, GEMM_SMEM>>>(
        attn_ptr, W_o, b_o, out, EE, EE);
}

// round 3
// speedup vs baseline: 2.0109x; 1.7820x over previous
#include <cuda_runtime.h>
#include <cuda_bf16.h>
#include <math.h>
#include <stdint.h>

// Problem constants
#define BB 2
#define SS 2048
#define DD 1024
#define EE 1024
#define HH 16
#define DKK 64
#define E3 3072
#define NROWS (BB*SS)    // 4096

// Scratch
__device__ float g_qkv[(size_t)NROWS * E3];           // fp32 QKV
__device__ uint32_t g_xh[(size_t)NROWS * DD / 2];     // bf16x2 packed
__device__ uint32_t g_xl[(size_t)NROWS * DD / 2];
__device__ uint32_t g_wqh[(size_t)E3 * DD / 2];
__device__ uint32_t g_wql[(size_t)E3 * DD / 2];
__device__ uint32_t g_woh[(size_t)EE * EE / 2];
__device__ uint32_t g_wol[(size_t)EE * EE / 2];
__device__ uint32_t g_ah[(size_t)NROWS * EE / 2];     // attention out hi
__device__ uint32_t g_al[(size_t)NROWS * EE / 2];     // attention out lo

// ---------------------------------------------------------------------------
// helpers
// ---------------------------------------------------------------------------
__device__ __forceinline__ uint32_t smem_u32(const void* p) {
    return (uint32_t)__cvta_generic_to_shared(p);
}
__device__ __forceinline__ void cp_async16(uint32_t s, const void* g) {
    asm volatile("cp.async.cg.shared.global [%0], [%1], 16;\n" :: "r"(s), "l"(g));
}
__device__ __forceinline__ void cp_commit() {
    asm volatile("cp.async.commit_group;\n" ::: "memory");
}
template <int N>
__device__ __forceinline__ void cp_wait() {
    asm volatile("cp.async.wait_group %0;\n" :: "n"(N) : "memory");
}
// pack (e0,e1) -> bf16x2 hi + residual lo (e0 in low half)
__device__ __forceinline__ void split2(float e0, float e1, uint32_t& hi, uint32_t& lo) {
    asm("cvt.rn.bf16x2.f32 %0, %1, %2;" : "=r"(hi) : "f"(e1), "f"(e0));
    float h0 = __uint_as_float(hi << 16);
    float h1 = __uint_as_float(hi & 0xffff0000u);
    asm("cvt.rn.bf16x2.f32 %0, %1, %2;" : "=r"(lo) : "f"(e1 - h1), "f"(e0 - h0));
}
__device__ __forceinline__ void mma_bf16(float* d, const uint32_t* a, const uint32_t* b) {
    asm volatile(
        "mma.sync.aligned.m16n8k16.row.col.f32.bf16.bf16.f32 "
        "{%0,%1,%2,%3}, {%4,%5,%6,%7}, {%8,%9}, {%0,%1,%2,%3};"
        : "+f"(d[0]), "+f"(d[1]), "+f"(d[2]), "+f"(d[3])
        : "r"(a[0]), "r"(a[1]), "r"(a[2]), "r"(a[3]), "r"(b[0]), "r"(b[1]));
}
__device__ __forceinline__ void ldsm4t(uint32_t* d, uint32_t a) {
    asm volatile("ldmatrix.sync.aligned.m8n8.x4.trans.shared.b16 {%0,%1,%2,%3}, [%4];"
        : "=r"(d[0]), "=r"(d[1]), "=r"(d[2]), "=r"(d[3]) : "r"(a));
}
// e^x for x <= 0, FMA-pipe only (no MUFU)
__device__ __forceinline__ float exp_neg(float x) {
    float y = fmaxf(x * 1.44269504f, -120.0f);
    int   n = __float2int_rn(y);
    float f = y - (float)n;
    float p = 1.33335581e-3f;
    p = fmaf(p, f, 9.61812910e-3f);
    p = fmaf(p, f, 5.55041087e-2f);
    p = fmaf(p, f, 2.40226507e-1f);
    p = fmaf(p, f, 6.93147180e-1f);
    p = fmaf(p, f, 1.0f);
    return p * __uint_as_float((uint32_t)(n + 127) << 23);
}

// ---------------------------------------------------------------------------
// split fp32 -> bf16 hi/lo (packed pairs)
// ---------------------------------------------------------------------------
__global__ __launch_bounds__(256) void split_kernel(
    const float* __restrict__ in, uint32_t* __restrict__ hi,
    uint32_t* __restrict__ lo, int n4)
{
    int i = blockIdx.x * 256 + threadIdx.x;
    if (i >= n4) return;
    float4 v = ((const float4*)in)[i];
    uint32_t h0, l0, h1, l1;
    split2(v.x, v.y, h0, l0);
    split2(v.z, v.w, h1, l1);
    hi[2 * i] = h0; hi[2 * i + 1] = h1;
    lo[2 * i] = l0; lo[2 * i + 1] = l1;
}

// ---------------------------------------------------------------------------
// bf16 3-pass split GEMM (NT): C[n][m] = sum_k A[n][k]*B[m][k] + bias[m]
// Block 128x128, BK=32, 256 threads = 8 warps (2x4), warp tile 64x32.
// smem tiles stride 40 bf16 (80B), double buffered, cp.async.
// ---------------------------------------------------------------------------
#define GBM 128
#define GBN 128
#define GBK 32
#define TSTRIDE 40                       // bf16 per row
#define TILE_B (GBM * TSTRIDE * 2)       // 10240 bytes per tile array
#define GEMM_SMEM (8 * TILE_B)           // 81920

__global__ __launch_bounds__(256) void gemm_bf16_kernel(
    const __nv_bfloat16* __restrict__ Ah, const __nv_bfloat16* __restrict__ Al,
    const __nv_bfloat16* __restrict__ Bh, const __nv_bfloat16* __restrict__ Bl,
    const float* __restrict__ bias, float* __restrict__ C, int K, int M)
{
    extern __shared__ char smc[];
    // layout per buffer: [AH][AL][BH][BL]
    const int tid = threadIdx.x;
    const int lane = tid & 31;
    const int warp = tid >> 5;
    const int wr = warp >> 2;
    const int wc = warp & 3;
    const int g  = lane >> 2;
    const int tg = lane & 3;

    const int n0 = blockIdx.y * GBM;
    const int m0 = blockIdx.x * GBN;

    const int ldr = tid >> 1;          // 0..127
    const int ldc = (tid & 1) * 2;     // chunk base (16B chunks)

    float acc[4][4][4];
#pragma unroll
    for (int mt = 0; mt < 4; mt++)
#pragma unroll
        for (int nt = 0; nt < 4; nt++)
#pragma unroll
            for (int i = 0; i < 4; i++) acc[mt][nt][i] = 0.f;

    const int KT = K / GBK;

    auto load_tile = [&](int kt) {
        int buf = kt & 1;
        char* base = smc + buf * 4 * TILE_B;
        const __nv_bfloat16* srcs[4] = {
            Ah + (size_t)(n0 + ldr) * K + kt * GBK,
            Al + (size_t)(n0 + ldr) * K + kt * GBK,
            Bh + (size_t)(m0 + ldr) * K + kt * GBK,
            Bl + (size_t)(m0 + ldr) * K + kt * GBK };
#pragma unroll
        for (int a = 0; a < 4; a++) {
            uint32_t dst = smem_u32(base + a * TILE_B + ldr * (TSTRIDE * 2) + ldc * 16);
            cp_async16(dst, srcs[a] + ldc * 8);
            cp_async16(dst + 16, srcs[a] + ldc * 8 + 8);
        }
    };

    load_tile(0); cp_commit();

    for (int kt = 0; kt < KT; kt++) {
        if (kt + 1 < KT) { load_tile(kt + 1); cp_commit(); cp_wait<1>(); }
        else cp_wait<0>();
        __syncthreads();

        char* base = smc + (kt & 1) * 4 * TILE_B;
        const uint32_t* AH = (const uint32_t*)(base);
        const uint32_t* AL = (const uint32_t*)(base + TILE_B);
        const uint32_t* BH = (const uint32_t*)(base + 2 * TILE_B);
        const uint32_t* BL = (const uint32_t*)(base + 3 * TILE_B);

#pragma unroll
        for (int ks = 0; ks < 2; ks++) {
            uint32_t ah[4][4], al[4][4];
#pragma unroll
            for (int mt = 0; mt < 4; mt++) {
                int ab = (wr * 64 + mt * 16 + g) * 20 + ks * 8 + tg;
                ah[mt][0] = AH[ab];       ah[mt][1] = AH[ab + 160];
                ah[mt][2] = AH[ab + 4];   ah[mt][3] = AH[ab + 164];
                al[mt][0] = AL[ab];       al[mt][1] = AL[ab + 160];
                al[mt][2] = AL[ab + 4];   al[mt][3] = AL[ab + 164];
            }
            uint32_t bh[4][2], bl[4][2];
#pragma unroll
            for (int nt = 0; nt < 4; nt++) {
                int bb = (wc * 32 + nt * 8 + g) * 20 + ks * 8 + tg;
                bh[nt][0] = BH[bb]; bh[nt][1] = BH[bb + 4];
                bl[nt][0] = BL[bb]; bl[nt][1] = BL[bb + 4];
            }
#pragma unroll
            for (int mt = 0; mt < 4; mt++)
#pragma unroll
                for (int nt = 0; nt < 4; nt++) {
                    mma_bf16(acc[mt][nt], ah[mt], bh[nt]);
                    mma_bf16(acc[mt][nt], al[mt], bh[nt]);
                    mma_bf16(acc[mt][nt], ah[mt], bl[nt]);
                }
        }
        __syncthreads();
    }

#pragma unroll
    for (int mt = 0; mt < 4; mt++) {
        int row = n0 + wr * 64 + mt * 16 + g;
#pragma unroll
        for (int nt = 0; nt < 4; nt++) {
            int col = m0 + wc * 32 + nt * 8 + 2 * tg;
            float b0 = bias[col], b1 = bias[col + 1];
            float2 v0 = make_float2(acc[mt][nt][0] + b0, acc[mt][nt][1] + b1);
            float2 v1 = make_float2(acc[mt][nt][2] + b0, acc[mt][nt][3] + b1);
            *(float2*)(C + (size_t)row * M + col) = v0;
            *(float2*)(C + (size_t)(row + 8) * M + col) = v1;
        }
    }
}

// ---------------------------------------------------------------------------
// Flash attention on bf16 mma, 3-pass split. One block = 128 queries of (b,h).
// 256 threads = 8 warps, warp = 16 query rows. KV chunks of 64.
// smem: fp32 staging (2 bufs) + bf16 hi/lo Q/K/V (stride 72 bf16).
// ---------------------------------------------------------------------------
#define AT_FK(buf)  ((buf) * 32768)          // K fp32 16KB
#define AT_FV(buf)  ((buf) * 32768 + 16384)  // V fp32 16KB
#define AT_QH 65536
#define AT_QL (AT_QH + 18432)
#define AT_KH (AT_QL + 18432)
#define AT_KL (AT_KH + 9216)
#define AT_VH (AT_KL + 9216)
#define AT_VL (AT_VH + 9216)
#define ATTN_SMEM (AT_VL + 9216)             // 139264

__global__ __launch_bounds__(256) void attn_kernel(
    const float* __restrict__ qkv, uint32_t* __restrict__ outh,
    uint32_t* __restrict__ outl)
{
    extern __shared__ char smc[];
    const int tid = threadIdx.x;
    const int lane = tid & 31;
    const int wid = tid >> 5;
    const int g  = lane >> 2;
    const int tg = lane & 3;
    const int b = blockIdx.z;
    const int h = blockIdx.y;
    const int q0 = blockIdx.x * 128;

    uint32_t* Qh = (uint32_t*)(smc + AT_QH);
    uint32_t* Ql = (uint32_t*)(smc + AT_QL);
    uint32_t* Kh = (uint32_t*)(smc + AT_KH);
    uint32_t* Kl = (uint32_t*)(smc + AT_KL);
    uint32_t* Vh = (uint32_t*)(smc + AT_VH);
    uint32_t* Vl = (uint32_t*)(smc + AT_VL);

    // ldmatrix per-lane address component
    const int lm_i = lane >> 3;
    const int lm_r = lane & 7;
    const int lm_k = ((lm_i & 1) << 3) + lm_r;
    const int lm_n = (lm_i >> 1) << 3;
    const uint32_t vh_lm = smem_u32(smc + AT_VH) + (uint32_t)(lm_k * 72 + lm_n) * 2;
    const uint32_t vl_lm = smem_u32(smc + AT_VL) + (uint32_t)(lm_k * 72 + lm_n) * 2;

    const size_t rowbase = (size_t)b * SS;

    // issue cp.async for KV chunk c
    auto issue_kv = [&](int c) {
        int buf = c & 1;
        int r = tid >> 2, cq = tid & 3;
        const float* krow = qkv + (rowbase + c * 64 + r) * E3 + h * 192 + 64;
        uint32_t ks_ = smem_u32(smc + AT_FK(buf) + r * 256);
        uint32_t vs_ = smem_u32(smc + AT_FV(buf) + r * 256);
#pragma unroll
        for (int j = 0; j < 4; j++) {
            int off = (cq * 4 + j) * 16;               // bytes
            cp_async16(ks_ + off, (const char*)krow + off);
            cp_async16(vs_ + off, (const char*)(krow + 64) + off);
        }
    };

    issue_kv(0); cp_commit();

    // stage Q (once): scale by 1/8, split into smem
    {
        int r = tid >> 1, hf = tid & 1;
        const float* qrow = qkv + (rowbase + q0 + r) * E3 + h * 192;
#pragma unroll
        for (int j = 0; j < 8; j++) {
            int c0 = hf * 32 + j * 4;
            float4 v = *(const float4*)(qrow + c0);
            v.x *= 0.125f; v.y *= 0.125f; v.z *= 0.125f; v.w *= 0.125f;
            uint32_t h0, l0, h1, l1;
            split2(v.x, v.y, h0, l0);
            split2(v.z, v.w, h1, l1);
            int idx = r * 36 + c0 / 2;
            Qh[idx] = h0; Qh[idx + 1] = h1;
            Ql[idx] = l0; Ql[idx + 1] = l1;
        }
    }

    float acco[8][4];
#pragma unroll
    for (int nt = 0; nt < 8; nt++)
#pragma unroll
        for (int i = 0; i < 4; i++) acco[nt][i] = 0.f;
    float m0 = -1e30f, m1 = -1e30f, l0 = 0.f, l1 = 0.f;

    const int wrow = wid * 16;

    for (int c = 0; c < SS / 64; c++) {
        if (c + 1 < SS / 64) { issue_kv(c + 1); cp_commit(); cp_wait<1>(); }
        else cp_wait<0>();
        __syncthreads();

        // convert fp32 chunk -> bf16 hi/lo smem
        {
            int buf = c & 1;
            const float* kf = (const float*)(smc + AT_FK(buf));
            const float* vf = (const float*)(smc + AT_FV(buf));
            int r = tid >> 2, cq = tid & 3;
#pragma unroll
            for (int j = 0; j < 4; j++) {
                int c0 = cq * 16 + j * 4;
                float4 kv = *(const float4*)(kf + r * 64 + c0);
                float4 vv = *(const float4*)(vf + r * 64 + c0);
                uint32_t h0, lo0, h1, lo1;
                int idx = r * 36 + c0 / 2;
                split2(kv.x, kv.y, h0, lo0); split2(kv.z, kv.w, h1, lo1);
                Kh[idx] = h0; Kh[idx + 1] = h1; Kl[idx] = lo0; Kl[idx + 1] = lo1;
                split2(vv.x, vv.y, h0, lo0); split2(vv.z, vv.w, h1, lo1);
                Vh[idx] = h0; Vh[idx + 1] = h1; Vl[idx] = lo0; Vl[idx + 1] = lo1;
            }
        }
        __syncthreads();

        // S = Q K^T (scaled Q)
        float accs[8][4];
#pragma unroll
        for (int nt = 0; nt < 8; nt++)
#pragma unroll
            for (int i = 0; i < 4; i++) accs[nt][i] = 0.f;

#pragma unroll
        for (int ks = 0; ks < 4; ks++) {
            uint32_t aqh[4], aql[4];
            int ab = (wrow + g) * 36 + ks * 8 + tg;
            aqh[0] = Qh[ab]; aqh[1] = Qh[ab + 288]; aqh[2] = Qh[ab + 4]; aqh[3] = Qh[ab + 292];
            aql[0] = Ql[ab]; aql[1] = Ql[ab + 288]; aql[2] = Ql[ab + 4]; aql[3] = Ql[ab + 292];
#pragma unroll
            for (int nt = 0; nt < 8; nt++) {
                int bb = (nt * 8 + g) * 36 + ks * 8 + tg;
                uint32_t bh[2] = { Kh[bb], Kh[bb + 4] };
                uint32_t bl[2] = { Kl[bb], Kl[bb + 4] };
                mma_bf16(accs[nt], aqh, bh);
                mma_bf16(accs[nt], aql, bh);
                mma_bf16(accs[nt], aqh, bl);
            }
        }

        // online softmax
        float rmax0 = -1e30f, rmax1 = -1e30f;
#pragma unroll
        for (int nt = 0; nt < 8; nt++) {
            rmax0 = fmaxf(rmax0, fmaxf(accs[nt][0], accs[nt][1]));
            rmax1 = fmaxf(rmax1, fmaxf(accs[nt][2], accs[nt][3]));
        }
#pragma unroll
        for (int off = 1; off <= 2; off <<= 1) {
            rmax0 = fmaxf(rmax0, __shfl_xor_sync(0xffffffffu, rmax0, off));
            rmax1 = fmaxf(rmax1, __shfl_xor_sync(0xffffffffu, rmax1, off));
        }
        float mn0 = fmaxf(m0, rmax0), mn1 = fmaxf(m1, rmax1);
        float a0 = exp_neg(m0 - mn0), a1 = exp_neg(m1 - mn1);
        m0 = mn0; m1 = mn1;
        float rs0 = 0.f, rs1 = 0.f;
#pragma unroll
        for (int nt = 0; nt < 8; nt++) {
            float p0 = exp_neg(accs[nt][0] - mn0);
            float p1 = exp_neg(accs[nt][1] - mn0);
            float p2 = exp_neg(accs[nt][2] - mn1);
            float p3 = exp_neg(accs[nt][3] - mn1);
            accs[nt][0] = p0; accs[nt][1] = p1; accs[nt][2] = p2; accs[nt][3] = p3;
            rs0 += p0 + p1; rs1 += p2 + p3;
        }
#pragma unroll
        for (int off = 1; off <= 2; off <<= 1) {
            rs0 += __shfl_xor_sync(0xffffffffu, rs0, off);
            rs1 += __shfl_xor_sync(0xffffffffu, rs1, off);
        }
        l0 = l0 * a0 + rs0; l1 = l1 * a1 + rs1;
#pragma unroll
        for (int nt = 0; nt < 8; nt++) {
            acco[nt][0] *= a0; acco[nt][1] *= a0;
            acco[nt][2] *= a1; acco[nt][3] *= a1;
        }

        // O += P V
#pragma unroll
        for (int ks = 0; ks < 4; ks++) {
            uint32_t ph[4], pl[4];
            split2(accs[2 * ks][0], accs[2 * ks][1], ph[0], pl[0]);
            split2(accs[2 * ks][2], accs[2 * ks][3], ph[1], pl[1]);
            split2(accs[2 * ks + 1][0], accs[2 * ks + 1][1], ph[2], pl[2]);
            split2(accs[2 * ks + 1][2], accs[2 * ks + 1][3], ph[3], pl[3]);
#pragma unroll
            for (int np = 0; np < 4; np++) {
                uint32_t bh4[4], bl4[4];
                ldsm4t(bh4, vh_lm + ks * 2304 + np * 32);
                ldsm4t(bl4, vl_lm + ks * 2304 + np * 32);
                mma_bf16(acco[2 * np], ph, bh4);
                mma_bf16(acco[2 * np], pl, bh4);
                mma_bf16(acco[2 * np], ph, bl4);
                mma_bf16(acco[2 * np + 1], ph, bh4 + 2);
                mma_bf16(acco[2 * np + 1], pl, bh4 + 2);
                mma_bf16(acco[2 * np + 1], ph, bl4 + 2);
            }
        }
    }

    // epilogue: normalize, split to bf16 hi/lo, store
    float inv0 = 1.0f / l0, inv1 = 1.0f / l1;
    int row0 = b * SS + q0 + wrow + g;
#pragma unroll
    for (int nt = 0; nt < 8; nt++) {
        int colh = h * 32 + nt * 4 + tg;      // packed-b32 column
        uint32_t hhi, hlo;
        split2(acco[nt][0] * inv0, acco[nt][1] * inv0, hhi, hlo);
        outh[(size_t)row0 * 512 + colh] = hhi;
        outl[(size_t)row0 * 512 + colh] = hlo;
        split2(acco[nt][2] * inv1, acco[nt][3] * inv1, hhi, hlo);
        outh[(size_t)(row0 + 8) * 512 + colh] = hhi;
        outl[(size_t)(row0 + 8) * 512 + colh] = hlo;
    }
}

// ---------------------------------------------------------------------------
extern "C" void kernel_launch(void* const* d_in, const int* in_sizes, int n_in,
                              void* d_out, int out_size)
{
    const float* x     = (const float*)d_in[0];
    const float* W_qkv = (const float*)d_in[1];
    const float* b_qkv = (const float*)d_in[2];
    const float* W_o   = (const float*)d_in[3];
    const float* b_o   = (const float*)d_in[4];
    float* out = (float*)d_out;

    float* qkv_ptr;
    uint32_t *xh, *xl, *wqh, *wql, *woh, *wol, *ah, *al;
    cudaGetSymbolAddress((void**)&qkv_ptr, g_qkv);
    cudaGetSymbolAddress((void**)&xh, g_xh);   cudaGetSymbolAddress((void**)&xl, g_xl);
    cudaGetSymbolAddress((void**)&wqh, g_wqh); cudaGetSymbolAddress((void**)&wql, g_wql);
    cudaGetSymbolAddress((void**)&woh, g_woh); cudaGetSymbolAddress((void**)&wol, g_wol);
    cudaGetSymbolAddress((void**)&ah, g_ah);   cudaGetSymbolAddress((void**)&al, g_al);

    cudaFuncSetAttribute(gemm_bf16_kernel,
                         cudaFuncAttributeMaxDynamicSharedMemorySize, GEMM_SMEM);
    cudaFuncSetAttribute(attn_kernel,
                         cudaFuncAttributeMaxDynamicSharedMemorySize, ATTN_SMEM);

    // 0) split inputs to bf16 hi/lo
    split_kernel<<<NROWS * DD / 4 / 256, 256>>>(x, xh, xl, NROWS * DD / 4);
    split_kernel<<<E3 * DD / 4 / 256, 256>>>(W_qkv, wqh, wql, E3 * DD / 4);
    split_kernel<<<EE * EE / 4 / 256, 256>>>(W_o, woh, wol, EE * EE / 4);

    // 1) QKV projection
    gemm_bf16_kernel<<<dim3(E3 / GBN, NROWS / GBM), 256, GEMM_SMEM>>>(
        (const __nv_bfloat16*)xh, (const __nv_bfloat16*)xl,
        (const __nv_bfloat16*)wqh, (const __nv_bfloat16*)wql,
        b_qkv, qkv_ptr, DD, E3);

    // 2) Attention (writes bf16 hi/lo)
    attn_kernel<<<dim3(SS / 128, HH, BB), 256, ATTN_SMEM>>>(qkv_ptr, ah, al);

    // 3) Output projection
    gemm_bf16_kernel<<<dim3(EE / GBN, NROWS / GBM), 256, GEMM_SMEM>>>(
        (const __nv_bfloat16*)ah, (const __nv_bfloat16*)al,
        (const __nv_bfloat16*)woh, (const __nv_bfloat16*)wol,
        b_o, out, EE, EE);
}

// round 4
// speedup vs baseline: 2.0110x; 1.0001x over previous
#include <cuda_runtime.h>
#include <cuda_bf16.h>
#include <math.h>
#include <stdint.h>

// Problem constants
#define BB 2
#define SS 2048
#define DD 1024
#define EE 1024
#define HH 16
#define DKK 64
#define E3 3072
#define NROWS (BB*SS)    // 4096

// Scratch
__device__ float g_qkv[(size_t)NROWS * E3];           // fp32 QKV
__device__ uint32_t g_xh[(size_t)NROWS * DD / 2];     // bf16x2 packed
__device__ uint32_t g_xl[(size_t)NROWS * DD / 2];
__device__ uint32_t g_wqh[(size_t)E3 * DD / 2];
__device__ uint32_t g_wql[(size_t)E3 * DD / 2];
__device__ uint32_t g_woh[(size_t)EE * EE / 2];
__device__ uint32_t g_wol[(size_t)EE * EE / 2];
__device__ uint32_t g_ah[(size_t)NROWS * EE / 2];     // attention out hi
__device__ uint32_t g_al[(size_t)NROWS * EE / 2];     // attention out lo

// ---------------------------------------------------------------------------
// helpers
// ---------------------------------------------------------------------------
__device__ __forceinline__ uint32_t smem_u32(const void* p) {
    return (uint32_t)__cvta_generic_to_shared(p);
}
__device__ __forceinline__ void cp_async16(uint32_t s, const void* g) {
    asm volatile("cp.async.cg.shared.global [%0], [%1], 16;\n" :: "r"(s), "l"(g));
}
__device__ __forceinline__ void cp_commit() {
    asm volatile("cp.async.commit_group;\n" ::: "memory");
}
template <int N>
__device__ __forceinline__ void cp_wait() {
    asm volatile("cp.async.wait_group %0;\n" :: "n"(N) : "memory");
}
// pack (e0,e1) -> bf16x2 hi + residual lo (e0 in low half)
__device__ __forceinline__ void split2(float e0, float e1, uint32_t& hi, uint32_t& lo) {
    asm("cvt.rn.bf16x2.f32 %0, %1, %2;" : "=r"(hi) : "f"(e1), "f"(e0));
    float h0 = __uint_as_float(hi << 16);
    float h1 = __uint_as_float(hi & 0xffff0000u);
    asm("cvt.rn.bf16x2.f32 %0, %1, %2;" : "=r"(lo) : "f"(e1 - h1), "f"(e0 - h0));
}
__device__ __forceinline__ void mma_bf16(float* d, const uint32_t* a, const uint32_t* b) {
    asm volatile(
        "mma.sync.aligned.m16n8k16.row.col.f32.bf16.bf16.f32 "
        "{%0,%1,%2,%3}, {%4,%5,%6,%7}, {%8,%9}, {%0,%1,%2,%3};"
        : "+f"(d[0]), "+f"(d[1]), "+f"(d[2]), "+f"(d[3])
        : "r"(a[0]), "r"(a[1]), "r"(a[2]), "r"(a[3]), "r"(b[0]), "r"(b[1]));
}
__device__ __forceinline__ void ldsm4t(uint32_t* d, uint32_t a) {
    asm volatile("ldmatrix.sync.aligned.m8n8.x4.trans.shared.b16 {%0,%1,%2,%3}, [%4];"
        : "=r"(d[0]), "=r"(d[1]), "=r"(d[2]), "=r"(d[3]) : "r"(a));
}
// e^x for x <= 0, FMA-pipe only (no MUFU)
__device__ __forceinline__ float exp_neg(float x) {
    float y = fmaxf(x * 1.44269504f, -120.0f);
    int   n = __float2int_rn(y);
    float f = y - (float)n;
    float p = 1.33335581e-3f;
    p = fmaf(p, f, 9.61812910e-3f);
    p = fmaf(p, f, 5.55041087e-2f);
    p = fmaf(p, f, 2.40226507e-1f);
    p = fmaf(p, f, 6.93147180e-1f);
    p = fmaf(p, f, 1.0f);
    return p * __uint_as_float((uint32_t)(n + 127) << 23);
}

// ---------------------------------------------------------------------------
// split fp32 -> bf16 hi/lo (packed pairs)
// ---------------------------------------------------------------------------
__global__ __launch_bounds__(256) void split_kernel(
    const float* __restrict__ in, uint32_t* __restrict__ hi,
    uint32_t* __restrict__ lo, int n4)
{
    int i = blockIdx.x * 256 + threadIdx.x;
    if (i >= n4) return;
    float4 v = ((const float4*)in)[i];
    uint32_t h0, l0, h1, l1;
    split2(v.x, v.y, h0, l0);
    split2(v.z, v.w, h1, l1);
    hi[2 * i] = h0; hi[2 * i + 1] = h1;
    lo[2 * i] = l0; lo[2 * i + 1] = l1;
}

// ---------------------------------------------------------------------------
// bf16 3-pass split GEMM (NT): C[n][m] = sum_k A[n][k]*B[m][k] + bias[m]
// Block 128x128, BK=32, 256 threads = 8 warps (2x4), warp tile 64x32.
// smem tiles stride 40 bf16 (80B), double buffered, cp.async.
// ---------------------------------------------------------------------------
#define GBM 128
#define GBN 128
#define GBK 32
#define TSTRIDE 40                       // bf16 per row
#define TILE_B (GBM * TSTRIDE * 2)       // 10240 bytes per tile array
#define GEMM_SMEM (8 * TILE_B)           // 81920

__global__ __launch_bounds__(256) void gemm_bf16_kernel(
    const __nv_bfloat16* __restrict__ Ah, const __nv_bfloat16* __restrict__ Al,
    const __nv_bfloat16* __restrict__ Bh, const __nv_bfloat16* __restrict__ Bl,
    const float* __restrict__ bias, float* __restrict__ C, int K, int M)
{
    extern __shared__ char smc[];
    // layout per buffer: [AH][AL][BH][BL]
    const int tid = threadIdx.x;
    const int lane = tid & 31;
    const int warp = tid >> 5;
    const int wr = warp >> 2;
    const int wc = warp & 3;
    const int g  = lane >> 2;
    const int tg = lane & 3;

    const int n0 = blockIdx.y * GBM;
    const int m0 = blockIdx.x * GBN;

    const int ldr = tid >> 1;          // 0..127
    const int ldc = (tid & 1) * 2;     // chunk base (16B chunks)

    float acc[4][4][4];
#pragma unroll
    for (int mt = 0; mt < 4; mt++)
#pragma unroll
        for (int nt = 0; nt < 4; nt++)
#pragma unroll
            for (int i = 0; i < 4; i++) acc[mt][nt][i] = 0.f;

    const int KT = K / GBK;

    auto load_tile = [&](int kt) {
        int buf = kt & 1;
        char* base = smc + buf * 4 * TILE_B;
        const __nv_bfloat16* srcs[4] = {
            Ah + (size_t)(n0 + ldr) * K + kt * GBK,
            Al + (size_t)(n0 + ldr) * K + kt * GBK,
            Bh + (size_t)(m0 + ldr) * K + kt * GBK,
            Bl + (size_t)(m0 + ldr) * K + kt * GBK };
#pragma unroll
        for (int a = 0; a < 4; a++) {
            uint32_t dst = smem_u32(base + a * TILE_B + ldr * (TSTRIDE * 2) + ldc * 16);
            cp_async16(dst, srcs[a] + ldc * 8);
            cp_async16(dst + 16, srcs[a] + ldc * 8 + 8);
        }
    };

    load_tile(0); cp_commit();

    for (int kt = 0; kt < KT; kt++) {
        if (kt + 1 < KT) { load_tile(kt + 1); cp_commit(); cp_wait<1>(); }
        else cp_wait<0>();
        __syncthreads();

        char* base = smc + (kt & 1) * 4 * TILE_B;
        const uint32_t* AH = (const uint32_t*)(base);
        const uint32_t* AL = (const uint32_t*)(base + TILE_B);
        const uint32_t* BH = (const uint32_t*)(base + 2 * TILE_B);
        const uint32_t* BL = (const uint32_t*)(base + 3 * TILE_B);

#pragma unroll
        for (int ks = 0; ks < 2; ks++) {
            uint32_t ah[4][4], al[4][4];
#pragma unroll
            for (int mt = 0; mt < 4; mt++) {
                int ab = (wr * 64 + mt * 16 + g) * 20 + ks * 8 + tg;
                ah[mt][0] = AH[ab];       ah[mt][1] = AH[ab + 160];
                ah[mt][2] = AH[ab + 4];   ah[mt][3] = AH[ab + 164];
                al[mt][0] = AL[ab];       al[mt][1] = AL[ab + 160];
                al[mt][2] = AL[ab + 4];   al[mt][3] = AL[ab + 164];
            }
            uint32_t bh[4][2], bl[4][2];
#pragma unroll
            for (int nt = 0; nt < 4; nt++) {
                int bb = (wc * 32 + nt * 8 + g) * 20 + ks * 8 + tg;
                bh[nt][0] = BH[bb]; bh[nt][1] = BH[bb + 4];
                bl[nt][0] = BL[bb]; bl[nt][1] = BL[bb + 4];
            }
#pragma unroll
            for (int mt = 0; mt < 4; mt++)
#pragma unroll
                for (int nt = 0; nt < 4; nt++) {
                    mma_bf16(acc[mt][nt], ah[mt], bh[nt]);
                    mma_bf16(acc[mt][nt], al[mt], bh[nt]);
                    mma_bf16(acc[mt][nt], ah[mt], bl[nt]);
                }
        }
        __syncthreads();
    }

#pragma unroll
    for (int mt = 0; mt < 4; mt++) {
        int row = n0 + wr * 64 + mt * 16 + g;
#pragma unroll
        for (int nt = 0; nt < 4; nt++) {
            int col = m0 + wc * 32 + nt * 8 + 2 * tg;
            float b0 = bias[col], b1 = bias[col + 1];
            float2 v0 = make_float2(acc[mt][nt][0] + b0, acc[mt][nt][1] + b1);
            float2 v1 = make_float2(acc[mt][nt][2] + b0, acc[mt][nt][3] + b1);
            *(float2*)(C + (size_t)row * M + col) = v0;
            *(float2*)(C + (size_t)(row + 8) * M + col) = v1;
        }
    }
}

// ---------------------------------------------------------------------------
// Flash attention on bf16 mma, 3-pass split. One block = 128 queries of (b,h).
// 256 threads = 8 warps, warp = 16 query rows. KV chunks of 64.
// smem: fp32 staging (2 bufs) + bf16 hi/lo Q/K/V (stride 72 bf16).
// ---------------------------------------------------------------------------
#define AT_FK(buf)  ((buf) * 32768)          // K fp32 16KB
#define AT_FV(buf)  ((buf) * 32768 + 16384)  // V fp32 16KB
#define AT_QH 65536
#define AT_QL (AT_QH + 18432)
#define AT_KH (AT_QL + 18432)
#define AT_KL (AT_KH + 9216)
#define AT_VH (AT_KL + 9216)
#define AT_VL (AT_VH + 9216)
#define ATTN_SMEM (AT_VL + 9216)             // 139264

__global__ __launch_bounds__(256) void attn_kernel(
    const float* __restrict__ qkv, uint32_t* __restrict__ outh,
    uint32_t* __restrict__ outl)
{
    extern __shared__ char smc[];
    const int tid = threadIdx.x;
    const int lane = tid & 31;
    const int wid = tid >> 5;
    const int g  = lane >> 2;
    const int tg = lane & 3;
    const int b = blockIdx.z;
    const int h = blockIdx.y;
    const int q0 = blockIdx.x * 128;

    uint32_t* Qh = (uint32_t*)(smc + AT_QH);
    uint32_t* Ql = (uint32_t*)(smc + AT_QL);
    uint32_t* Kh = (uint32_t*)(smc + AT_KH);
    uint32_t* Kl = (uint32_t*)(smc + AT_KL);
    uint32_t* Vh = (uint32_t*)(smc + AT_VH);
    uint32_t* Vl = (uint32_t*)(smc + AT_VL);

    // ldmatrix per-lane address component
    const int lm_i = lane >> 3;
    const int lm_r = lane & 7;
    const int lm_k = ((lm_i & 1) << 3) + lm_r;
    const int lm_n = (lm_i >> 1) << 3;
    const uint32_t vh_lm = smem_u32(smc + AT_VH) + (uint32_t)(lm_k * 72 + lm_n) * 2;
    const uint32_t vl_lm = smem_u32(smc + AT_VL) + (uint32_t)(lm_k * 72 + lm_n) * 2;

    const size_t rowbase = (size_t)b * SS;

    // issue cp.async for KV chunk c
    auto issue_kv = [&](int c) {
        int buf = c & 1;
        int r = tid >> 2, cq = tid & 3;
        const float* krow = qkv + (rowbase + c * 64 + r) * E3 + h * 192 + 64;
        uint32_t ks_ = smem_u32(smc + AT_FK(buf) + r * 256);
        uint32_t vs_ = smem_u32(smc + AT_FV(buf) + r * 256);
#pragma unroll
        for (int j = 0; j < 4; j++) {
            int off = (cq * 4 + j) * 16;               // bytes
            cp_async16(ks_ + off, (const char*)krow + off);
            cp_async16(vs_ + off, (const char*)(krow + 64) + off);
        }
    };

    issue_kv(0); cp_commit();

    // stage Q (once): scale by 1/8, split into smem
    {
        int r = tid >> 1, hf = tid & 1;
        const float* qrow = qkv + (rowbase + q0 + r) * E3 + h * 192;
#pragma unroll
        for (int j = 0; j < 8; j++) {
            int c0 = hf * 32 + j * 4;
            float4 v = *(const float4*)(qrow + c0);
            v.x *= 0.125f; v.y *= 0.125f; v.z *= 0.125f; v.w *= 0.125f;
            uint32_t h0, l0, h1, l1;
            split2(v.x, v.y, h0, l0);
            split2(v.z, v.w, h1, l1);
            int idx = r * 36 + c0 / 2;
            Qh[idx] = h0; Qh[idx + 1] = h1;
            Ql[idx] = l0; Ql[idx + 1] = l1;
        }
    }

    float acco[8][4];
#pragma unroll
    for (int nt = 0; nt < 8; nt++)
#pragma unroll
        for (int i = 0; i < 4; i++) acco[nt][i] = 0.f;
    float m0 = -1e30f, m1 = -1e30f, l0 = 0.f, l1 = 0.f;

    const int wrow = wid * 16;

    for (int c = 0; c < SS / 64; c++) {
        if (c + 1 < SS / 64) { issue_kv(c + 1); cp_commit(); cp_wait<1>(); }
        else cp_wait<0>();
        __syncthreads();

        // convert fp32 chunk -> bf16 hi/lo smem
        {
            int buf = c & 1;
            const float* kf = (const float*)(smc + AT_FK(buf));
            const float* vf = (const float*)(smc + AT_FV(buf));
            int r = tid >> 2, cq = tid & 3;
#pragma unroll
            for (int j = 0; j < 4; j++) {
                int c0 = cq * 16 + j * 4;
                float4 kv = *(const float4*)(kf + r * 64 + c0);
                float4 vv = *(const float4*)(vf + r * 64 + c0);
                uint32_t h0, lo0, h1, lo1;
                int idx = r * 36 + c0 / 2;
                split2(kv.x, kv.y, h0, lo0); split2(kv.z, kv.w, h1, lo1);
                Kh[idx] = h0; Kh[idx + 1] = h1; Kl[idx] = lo0; Kl[idx + 1] = lo1;
                split2(vv.x, vv.y, h0, lo0); split2(vv.z, vv.w, h1, lo1);
                Vh[idx] = h0; Vh[idx + 1] = h1; Vl[idx] = lo0; Vl[idx + 1] = lo1;
            }
        }
        __syncthreads();

        // S = Q K^T (scaled Q)
        float accs[8][4];
#pragma unroll
        for (int nt = 0; nt < 8; nt++)
#pragma unroll
            for (int i = 0; i < 4; i++) accs[nt][i] = 0.f;

#pragma unroll
        for (int ks = 0; ks < 4; ks++) {
            uint32_t aqh[4], aql[4];
            int ab = (wrow + g) * 36 + ks * 8 + tg;
            aqh[0] = Qh[ab]; aqh[1] = Qh[ab + 288]; aqh[2] = Qh[ab + 4]; aqh[3] = Qh[ab + 292];
            aql[0] = Ql[ab]; aql[1] = Ql[ab + 288]; aql[2] = Ql[ab + 4]; aql[3] = Ql[ab + 292];
#pragma unroll
            for (int nt = 0; nt < 8; nt++) {
                int bb = (nt * 8 + g) * 36 + ks * 8 + tg;
                uint32_t bh[2] = { Kh[bb], Kh[bb + 4] };
                uint32_t bl[2] = { Kl[bb], Kl[bb + 4] };
                mma_bf16(accs[nt], aqh, bh);
                mma_bf16(accs[nt], aql, bh);
                mma_bf16(accs[nt], aqh, bl);
            }
        }

        // online softmax
        float rmax0 = -1e30f, rmax1 = -1e30f;
#pragma unroll
        for (int nt = 0; nt < 8; nt++) {
            rmax0 = fmaxf(rmax0, fmaxf(accs[nt][0], accs[nt][1]));
            rmax1 = fmaxf(rmax1, fmaxf(accs[nt][2], accs[nt][3]));
        }
#pragma unroll
        for (int off = 1; off <= 2; off <<= 1) {
            rmax0 = fmaxf(rmax0, __shfl_xor_sync(0xffffffffu, rmax0, off));
            rmax1 = fmaxf(rmax1, __shfl_xor_sync(0xffffffffu, rmax1, off));
        }
        float mn0 = fmaxf(m0, rmax0), mn1 = fmaxf(m1, rmax1);
        float a0 = exp_neg(m0 - mn0), a1 = exp_neg(m1 - mn1);
        m0 = mn0; m1 = mn1;
        float rs0 = 0.f, rs1 = 0.f;
#pragma unroll
        for (int nt = 0; nt < 8; nt++) {
            float p0 = exp_neg(accs[nt][0] - mn0);
            float p1 = exp_neg(accs[nt][1] - mn0);
            float p2 = exp_neg(accs[nt][2] - mn1);
            float p3 = exp_neg(accs[nt][3] - mn1);
            accs[nt][0] = p0; accs[nt][1] = p1; accs[nt][2] = p2; accs[nt][3] = p3;
            rs0 += p0 + p1; rs1 += p2 + p3;
        }
#pragma unroll
        for (int off = 1; off <= 2; off <<= 1) {
            rs0 += __shfl_xor_sync(0xffffffffu, rs0, off);
            rs1 += __shfl_xor_sync(0xffffffffu, rs1, off);
        }
        l0 = l0 * a0 + rs0; l1 = l1 * a1 + rs1;
#pragma unroll
        for (int nt = 0; nt < 8; nt++) {
            acco[nt][0] *= a0; acco[nt][1] *= a0;
            acco[nt][2] *= a1; acco[nt][3] *= a1;
        }

        // O += P V
#pragma unroll
        for (int ks = 0; ks < 4; ks++) {
            uint32_t ph[4], pl[4];
            split2(accs[2 * ks][0], accs[2 * ks][1], ph[0], pl[0]);
            split2(accs[2 * ks][2], accs[2 * ks][3], ph[1], pl[1]);
            split2(accs[2 * ks + 1][0], accs[2 * ks + 1][1], ph[2], pl[2]);
            split2(accs[2 * ks + 1][2], accs[2 * ks + 1][3], ph[3], pl[3]);
#pragma unroll
            for (int np = 0; np < 4; np++) {
                uint32_t bh4[4], bl4[4];
                ldsm4t(bh4, vh_lm + ks * 2304 + np * 32);
                ldsm4t(bl4, vl_lm + ks * 2304 + np * 32);
                mma_bf16(acco[2 * np], ph, bh4);
                mma_bf16(acco[2 * np], pl, bh4);
                mma_bf16(acco[2 * np], ph, bl4);
                mma_bf16(acco[2 * np + 1], ph, bh4 + 2);
                mma_bf16(acco[2 * np + 1], pl, bh4 + 2);
                mma_bf16(acco[2 * np + 1], ph, bl4 + 2);
            }
        }
    }

    // epilogue: normalize, split to bf16 hi/lo, store
    float inv0 = 1.0f / l0, inv1 = 1.0f / l1;
    int row0 = b * SS + q0 + wrow + g;
#pragma unroll
    for (int nt = 0; nt < 8; nt++) {
        int colh = h * 32 + nt * 4 + tg;      // packed-b32 column
        uint32_t hhi, hlo;
        split2(acco[nt][0] * inv0, acco[nt][1] * inv0, hhi, hlo);
        outh[(size_t)row0 * 512 + colh] = hhi;
        outl[(size_t)row0 * 512 + colh] = hlo;
        split2(acco[nt][2] * inv1, acco[nt][3] * inv1, hhi, hlo);
        outh[(size_t)(row0 + 8) * 512 + colh] = hhi;
        outl[(size_t)(row0 + 8) * 512 + colh] = hlo;
    }
}

// ---------------------------------------------------------------------------
extern "C" void kernel_launch(void* const* d_in, const int* in_sizes, int n_in,
                              void* d_out, int out_size)
{
    const float* x     = (const float*)d_in[0];
    const float* W_qkv = (const float*)d_in[1];
    const float* b_qkv = (const float*)d_in[2];
    const float* W_o   = (const float*)d_in[3];
    const float* b_o   = (const float*)d_in[4];
    float* out = (float*)d_out;

    float* qkv_ptr;
    uint32_t *xh, *xl, *wqh, *wql, *woh, *wol, *ah, *al;
    cudaGetSymbolAddress((void**)&qkv_ptr, g_qkv);
    cudaGetSymbolAddress((void**)&xh, g_xh);   cudaGetSymbolAddress((void**)&xl, g_xl);
    cudaGetSymbolAddress((void**)&wqh, g_wqh); cudaGetSymbolAddress((void**)&wql, g_wql);
    cudaGetSymbolAddress((void**)&woh, g_woh); cudaGetSymbolAddress((void**)&wol, g_wol);
    cudaGetSymbolAddress((void**)&ah, g_ah);   cudaGetSymbolAddress((void**)&al, g_al);

    cudaFuncSetAttribute(gemm_bf16_kernel,
                         cudaFuncAttributeMaxDynamicSharedMemorySize, GEMM_SMEM);
    cudaFuncSetAttribute(attn_kernel,
                         cudaFuncAttributeMaxDynamicSharedMemorySize, ATTN_SMEM);

    // 0) split inputs to bf16 hi/lo
    split_kernel<<<NROWS * DD / 4 / 256, 256>>>(x, xh, xl, NROWS * DD / 4);
    split_kernel<<<E3 * DD / 4 / 256, 256>>>(W_qkv, wqh, wql, E3 * DD / 4);
    split_kernel<<<EE * EE / 4 / 256, 256>>>(W_o, woh, wol, EE * EE / 4);

    // 1) QKV projection
    gemm_bf16_kernel<<<dim3(E3 / GBN, NROWS / GBM), 256, GEMM_SMEM>>>(
        (const __nv_bfloat16*)xh, (const __nv_bfloat16*)xl,
        (const __nv_bfloat16*)wqh, (const __nv_bfloat16*)wql,
        b_qkv, qkv_ptr, DD, E3);

    // 2) Attention (writes bf16 hi/lo)
    attn_kernel<<<dim3(SS / 128, HH, BB), 256, ATTN_SMEM>>>(qkv_ptr, ah, al);

    // 3) Output projection
    gemm_bf16_kernel<<<dim3(EE / GBN, NROWS / GBM), 256, GEMM_SMEM>>>(
        (const __nv_bfloat16*)ah, (const __nv_bfloat16*)al,
        (const __nv_bfloat16*)woh, (const __nv_bfloat16*)wol,
        b_o, out, EE, EE);
}

// round 5
// speedup vs baseline: 2.6313x; 1.3084x over previous
#include <cuda_runtime.h>
#include <cuda_bf16.h>
#include <math.h>
#include <stdint.h>

// Problem constants
#define BB 2
#define SS 2048
#define DD 1024
#define EE 1024
#define HH 16
#define DKK 64
#define E3 3072
#define NROWS (BB*SS)    // 4096
#define NC (SS/64)       // 32 KV chunks

// Scratch: all activations/weights kept as packed bf16x2 hi/lo
__device__ uint32_t g_xh[(size_t)NROWS * DD / 2];
__device__ uint32_t g_xl[(size_t)NROWS * DD / 2];
__device__ uint32_t g_wqh[(size_t)E3 * DD / 2];
__device__ uint32_t g_wql[(size_t)E3 * DD / 2];
__device__ uint32_t g_woh[(size_t)EE * EE / 2];
__device__ uint32_t g_wol[(size_t)EE * EE / 2];
__device__ uint32_t g_qkvh[(size_t)NROWS * E3 / 2];  // [row][1536 u32]
__device__ uint32_t g_qkvl[(size_t)NROWS * E3 / 2];
__device__ uint32_t g_ah[(size_t)NROWS * EE / 2];    // attention out hi
__device__ uint32_t g_al[(size_t)NROWS * EE / 2];

// ---------------------------------------------------------------------------
// helpers
// ---------------------------------------------------------------------------
__device__ __forceinline__ uint32_t smem_u32(const void* p) {
    return (uint32_t)__cvta_generic_to_shared(p);
}
__device__ __forceinline__ void cp_async16(uint32_t s, const void* g) {
    asm volatile("cp.async.cg.shared.global [%0], [%1], 16;\n" :: "r"(s), "l"(g));
}
__device__ __forceinline__ void cp_commit() {
    asm volatile("cp.async.commit_group;\n" ::: "memory");
}
template <int N>
__device__ __forceinline__ void cp_wait() {
    asm volatile("cp.async.wait_group %0;\n" :: "n"(N) : "memory");
}
__device__ __forceinline__ void split2(float e0, float e1, uint32_t& hi, uint32_t& lo) {
    asm("cvt.rn.bf16x2.f32 %0, %1, %2;" : "=r"(hi) : "f"(e1), "f"(e0));
    float h0 = __uint_as_float(hi << 16);
    float h1 = __uint_as_float(hi & 0xffff0000u);
    asm("cvt.rn.bf16x2.f32 %0, %1, %2;" : "=r"(lo) : "f"(e1 - h1), "f"(e0 - h0));
}
__device__ __forceinline__ void mma_bf16(float* d, const uint32_t* a, const uint32_t* b) {
    asm volatile(
        "mma.sync.aligned.m16n8k16.row.col.f32.bf16.bf16.f32 "
        "{%0,%1,%2,%3}, {%4,%5,%6,%7}, {%8,%9}, {%0,%1,%2,%3};"
        : "+f"(d[0]), "+f"(d[1]), "+f"(d[2]), "+f"(d[3])
        : "r"(a[0]), "r"(a[1]), "r"(a[2]), "r"(a[3]), "r"(b[0]), "r"(b[1]));
}
__device__ __forceinline__ void ldsm4t(uint32_t* d, uint32_t a) {
    asm volatile("ldmatrix.sync.aligned.m8n8.x4.trans.shared.b16 {%0,%1,%2,%3}, [%4];"
        : "=r"(d[0]), "=r"(d[1]), "=r"(d[2]), "=r"(d[3]) : "r"(a));
}
// e^x for x <= 0, FMA-pipe only
__device__ __forceinline__ float exp_neg(float x) {
    float y = fmaxf(x * 1.44269504f, -120.0f);
    int   n = __float2int_rn(y);
    float f = y - (float)n;
    float p = 1.33335581e-3f;
    p = fmaf(p, f, 9.61812910e-3f);
    p = fmaf(p, f, 5.55041087e-2f);
    p = fmaf(p, f, 2.40226507e-1f);
    p = fmaf(p, f, 6.93147180e-1f);
    p = fmaf(p, f, 1.0f);
    return p * __uint_as_float((uint32_t)(n + 127) << 23);
}

// ---------------------------------------------------------------------------
// split fp32 -> bf16 hi/lo (packed pairs)
// ---------------------------------------------------------------------------
__global__ __launch_bounds__(256) void split_kernel(
    const float* __restrict__ in, uint32_t* __restrict__ hi,
    uint32_t* __restrict__ lo, int n4)
{
    int i = blockIdx.x * 256 + threadIdx.x;
    if (i >= n4) return;
    float4 v = ((const float4*)in)[i];
    uint32_t h0, l0, h1, l1;
    split2(v.x, v.y, h0, l0);
    split2(v.z, v.w, h1, l1);
    hi[2 * i] = h0; hi[2 * i + 1] = h1;
    lo[2 * i] = l0; lo[2 * i + 1] = l1;
}

// ---------------------------------------------------------------------------
// bf16 3-pass split GEMM (NT): C[n][m] = sum_k A[n][k]*B[m][k] + bias[m]
// Block 128x128, BK=32, 256 threads = 8 warps (2x4), warp tile 64x32.
// Output: fp32 (Cf) OR packed bf16 hi/lo (Ch/Cl).
// ---------------------------------------------------------------------------
#define GBM 128
#define GBK 32
#define TSTRIDE 20                       // u32 per smem row (40 bf16)
#define TILE_B (GBM * TSTRIDE * 4)       // 10240 bytes
#define GEMM_SMEM (8 * TILE_B)           // 81920

__global__ __launch_bounds__(256, 2) void gemm_bf16_kernel(
    const uint32_t* __restrict__ Ah, const uint32_t* __restrict__ Al,
    const uint32_t* __restrict__ Bh, const uint32_t* __restrict__ Bl,
    const float* __restrict__ bias, float* __restrict__ Cf,
    uint32_t* __restrict__ Ch, uint32_t* __restrict__ Cl, int K, int M)
{
    extern __shared__ char smc[];
    const int tid = threadIdx.x;
    const int lane = tid & 31;
    const int warp = tid >> 5;
    const int wr = warp >> 2;
    const int wc = warp & 3;
    const int g  = lane >> 2;
    const int tg = lane & 3;

    const int n0 = blockIdx.y * GBM;
    const int m0 = blockIdx.x * GBM;
    const int K2 = K >> 1, M2 = M >> 1;

    const int ldr = tid >> 1;          // 0..127
    const int hf  = tid & 1;

    float acc[4][4][4];
#pragma unroll
    for (int mt = 0; mt < 4; mt++)
#pragma unroll
        for (int nt = 0; nt < 4; nt++)
#pragma unroll
            for (int i = 0; i < 4; i++) acc[mt][nt][i] = 0.f;

    const int KT = K / GBK;

    auto load_tile = [&](int kt) {
        char* base = smc + (kt & 1) * 4 * TILE_B;
        const uint32_t* srcs[4] = {
            Ah + (size_t)(n0 + ldr) * K2 + kt * 16 + hf * 8,
            Al + (size_t)(n0 + ldr) * K2 + kt * 16 + hf * 8,
            Bh + (size_t)(m0 + ldr) * K2 + kt * 16 + hf * 8,
            Bl + (size_t)(m0 + ldr) * K2 + kt * 16 + hf * 8 };
#pragma unroll
        for (int a = 0; a < 4; a++) {
            uint32_t dst = smem_u32(base + a * TILE_B + ldr * 80 + hf * 32);
            cp_async16(dst, srcs[a]);
            cp_async16(dst + 16, srcs[a] + 4);
        }
    };

    load_tile(0); cp_commit();

    for (int kt = 0; kt < KT; kt++) {
        if (kt + 1 < KT) { load_tile(kt + 1); cp_commit(); cp_wait<1>(); }
        else cp_wait<0>();
        __syncthreads();

        char* base = smc + (kt & 1) * 4 * TILE_B;
        const uint32_t* AH = (const uint32_t*)(base);
        const uint32_t* AL = (const uint32_t*)(base + TILE_B);
        const uint32_t* BH = (const uint32_t*)(base + 2 * TILE_B);
        const uint32_t* BL = (const uint32_t*)(base + 3 * TILE_B);

#pragma unroll
        for (int ks = 0; ks < 2; ks++) {
            uint32_t bh[4][2], bl[4][2];
#pragma unroll
            for (int nt = 0; nt < 4; nt++) {
                int bb = (wc * 32 + nt * 8 + g) * 20 + ks * 8 + tg;
                bh[nt][0] = BH[bb]; bh[nt][1] = BH[bb + 4];
                bl[nt][0] = BL[bb]; bl[nt][1] = BL[bb + 4];
            }
#pragma unroll
            for (int mt = 0; mt < 4; mt++) {
                uint32_t ah[4], al[4];
                int ab = (wr * 64 + mt * 16 + g) * 20 + ks * 8 + tg;
                ah[0] = AH[ab];     ah[1] = AH[ab + 160];
                ah[2] = AH[ab + 4]; ah[3] = AH[ab + 164];
                al[0] = AL[ab];     al[1] = AL[ab + 160];
                al[2] = AL[ab + 4]; al[3] = AL[ab + 164];
#pragma unroll
                for (int nt = 0; nt < 4; nt++) {
                    mma_bf16(acc[mt][nt], ah, bh[nt]);
                    mma_bf16(acc[mt][nt], al, bh[nt]);
                    mma_bf16(acc[mt][nt], ah, bl[nt]);
                }
            }
        }
        __syncthreads();
    }

#pragma unroll
    for (int mt = 0; mt < 4; mt++) {
        int row = n0 + wr * 64 + mt * 16 + g;
#pragma unroll
        for (int nt = 0; nt < 4; nt++) {
            int col = m0 + wc * 32 + nt * 8 + 2 * tg;
            float b0 = bias[col], b1 = bias[col + 1];
            float c00 = acc[mt][nt][0] + b0, c01 = acc[mt][nt][1] + b1;
            float c10 = acc[mt][nt][2] + b0, c11 = acc[mt][nt][3] + b1;
            if (Cf) {
                *(float2*)(Cf + (size_t)row * M + col) = make_float2(c00, c01);
                *(float2*)(Cf + (size_t)(row + 8) * M + col) = make_float2(c10, c11);
            } else {
                uint32_t hi, lo;
                split2(c00, c01, hi, lo);
                Ch[(size_t)row * M2 + (col >> 1)] = hi;
                Cl[(size_t)row * M2 + (col >> 1)] = lo;
                split2(c10, c11, hi, lo);
                Ch[(size_t)(row + 8) * M2 + (col >> 1)] = hi;
                Cl[(size_t)(row + 8) * M2 + (col >> 1)] = lo;
            }
        }
    }
}

// ---------------------------------------------------------------------------
// Flash attention on bf16 mma, 3-pass split, direct pre-split KV loads.
// One block = 128 queries of (b,h). 256 threads = 8 warps x 16 query rows.
// smem: Q hi/lo (128x36 u32) + double-buffered K/V hi/lo (64x36 u32 each).
// ---------------------------------------------------------------------------
#define AT_QH 0
#define AT_QL 18432
#define AT_KV(buf) (36864 + (buf) * 36864)
#define KV_KH 0
#define KV_KL 9216
#define KV_VH 18432
#define KV_VL 27648
#define ATTN_SMEM (36864 + 2 * 36864)    // 110592

__global__ __launch_bounds__(256, 2) void attn_kernel(
    const uint32_t* __restrict__ qh, const uint32_t* __restrict__ ql,
    uint32_t* __restrict__ outh, uint32_t* __restrict__ outl)
{
    extern __shared__ char smc[];
    const int tid = threadIdx.x;
    const int lane = tid & 31;
    const int wid = tid >> 5;
    const int g  = lane >> 2;
    const int tg = lane & 3;
    const int b = blockIdx.z;
    const int h = blockIdx.y;
    const int q0 = blockIdx.x * 128;

    const size_t rowbase = (size_t)b * SS;
    const int RS = 1536;  // u32 row stride of packed qkv

    uint32_t* Qh = (uint32_t*)(smc + AT_QH);
    uint32_t* Ql = (uint32_t*)(smc + AT_QL);

    // ldmatrix per-lane address component for V
    const int lm_i = lane >> 3;
    const int lm_r = lane & 7;
    const int lm_k = ((lm_i & 1) << 3) + lm_r;
    const int lm_n = (lm_i >> 1) << 3;
    const uint32_t lm_off = (uint32_t)(lm_k * 72 + lm_n) * 2;

    auto issue_kv = [&](int c) {
        int r = tid >> 2, q = tid & 3;
        size_t grow = (rowbase + c * 64 + r) * RS + h * 96;
        uint32_t dst = smem_u32(smc + AT_KV(c & 1) + r * 144 + q * 32);
        const uint32_t* s;
        s = qh + grow + 32 + q * 8;                       // K hi
        cp_async16(dst + KV_KH, s); cp_async16(dst + KV_KH + 16, s + 4);
        s = ql + grow + 32 + q * 8;                       // K lo
        cp_async16(dst + KV_KL, s); cp_async16(dst + KV_KL + 16, s + 4);
        s = qh + grow + 64 + q * 8;                       // V hi
        cp_async16(dst + KV_VH, s); cp_async16(dst + KV_VH + 16, s + 4);
        s = ql + grow + 64 + q * 8;                       // V lo
        cp_async16(dst + KV_VL, s); cp_async16(dst + KV_VL + 16, s + 4);
    };

    issue_kv(0); cp_commit();

    // Q tile: direct cp.async of pre-split bf16
    {
        int r = tid >> 1, hf = tid & 1;
        size_t grow = (rowbase + q0 + r) * RS + h * 96 + hf * 16;
        uint32_t dqh = smem_u32(smc + AT_QH + r * 144 + hf * 64);
        uint32_t dql = smem_u32(smc + AT_QL + r * 144 + hf * 64);
#pragma unroll
        for (int j = 0; j < 4; j++) {
            cp_async16(dqh + j * 16, qh + grow + j * 4);
            cp_async16(dql + j * 16, ql + grow + j * 4);
        }
    }
    cp_commit();

    float acco[8][4];
#pragma unroll
    for (int nt = 0; nt < 8; nt++)
#pragma unroll
        for (int i = 0; i < 4; i++) acco[nt][i] = 0.f;
    float m0 = -1e30f, m1 = -1e30f, l0 = 0.f, l1 = 0.f;

    const int wrow = wid * 16;

    for (int c = 0; c < NC; c++) {
        if (c + 1 < NC) { issue_kv(c + 1); cp_commit(); cp_wait<1>(); }
        else cp_wait<0>();
        __syncthreads();

        char* kvb = smc + AT_KV(c & 1);
        const uint32_t* Kh = (const uint32_t*)(kvb + KV_KH);
        const uint32_t* Kl = (const uint32_t*)(kvb + KV_KL);
        const uint32_t vh_lm = smem_u32(kvb + KV_VH) + lm_off;
        const uint32_t vl_lm = smem_u32(kvb + KV_VL) + lm_off;

        // S = Q K^T
        float accs[8][4];
#pragma unroll
        for (int nt = 0; nt < 8; nt++)
#pragma unroll
            for (int i = 0; i < 4; i++) accs[nt][i] = 0.f;

#pragma unroll
        for (int ks = 0; ks < 4; ks++) {
            uint32_t aqh[4], aql[4];
            int ab = (wrow + g) * 36 + ks * 8 + tg;
            aqh[0] = Qh[ab]; aqh[1] = Qh[ab + 288]; aqh[2] = Qh[ab + 4]; aqh[3] = Qh[ab + 292];
            aql[0] = Ql[ab]; aql[1] = Ql[ab + 288]; aql[2] = Ql[ab + 4]; aql[3] = Ql[ab + 292];
#pragma unroll
            for (int nt = 0; nt < 8; nt++) {
                int bb = (nt * 8 + g) * 36 + ks * 8 + tg;
                uint32_t bh[2] = { Kh[bb], Kh[bb + 4] };
                uint32_t bl[2] = { Kl[bb], Kl[bb + 4] };
                mma_bf16(accs[nt], aqh, bh);
                mma_bf16(accs[nt], aql, bh);
                mma_bf16(accs[nt], aqh, bl);
            }
        }

        // scale + online softmax
        float rmax0 = -1e30f, rmax1 = -1e30f;
#pragma unroll
        for (int nt = 0; nt < 8; nt++) {
#pragma unroll
            for (int i = 0; i < 4; i++) accs[nt][i] *= 0.125f;
            rmax0 = fmaxf(rmax0, fmaxf(accs[nt][0], accs[nt][1]));
            rmax1 = fmaxf(rmax1, fmaxf(accs[nt][2], accs[nt][3]));
        }
#pragma unroll
        for (int off = 1; off <= 2; off <<= 1) {
            rmax0 = fmaxf(rmax0, __shfl_xor_sync(0xffffffffu, rmax0, off));
            rmax1 = fmaxf(rmax1, __shfl_xor_sync(0xffffffffu, rmax1, off));
        }
        float mn0 = fmaxf(m0, rmax0), mn1 = fmaxf(m1, rmax1);
        float a0 = exp_neg(m0 - mn0), a1 = exp_neg(m1 - mn1);
        m0 = mn0; m1 = mn1;
        float rs0 = 0.f, rs1 = 0.f;
#pragma unroll
        for (int nt = 0; nt < 8; nt++) {
            float p0 = exp_neg(accs[nt][0] - mn0);
            float p1 = exp_neg(accs[nt][1] - mn0);
            float p2 = exp_neg(accs[nt][2] - mn1);
            float p3 = exp_neg(accs[nt][3] - mn1);
            accs[nt][0] = p0; accs[nt][1] = p1; accs[nt][2] = p2; accs[nt][3] = p3;
            rs0 += p0 + p1; rs1 += p2 + p3;
        }
#pragma unroll
        for (int off = 1; off <= 2; off <<= 1) {
            rs0 += __shfl_xor_sync(0xffffffffu, rs0, off);
            rs1 += __shfl_xor_sync(0xffffffffu, rs1, off);
        }
        l0 = l0 * a0 + rs0; l1 = l1 * a1 + rs1;
#pragma unroll
        for (int nt = 0; nt < 8; nt++) {
            acco[nt][0] *= a0; acco[nt][1] *= a0;
            acco[nt][2] *= a1; acco[nt][3] *= a1;
        }

        // O += P V
#pragma unroll
        for (int ks = 0; ks < 4; ks++) {
            uint32_t ph[4], pl[4];
            split2(accs[2 * ks][0], accs[2 * ks][1], ph[0], pl[0]);
            split2(accs[2 * ks][2], accs[2 * ks][3], ph[1], pl[1]);
            split2(accs[2 * ks + 1][0], accs[2 * ks + 1][1], ph[2], pl[2]);
            split2(accs[2 * ks + 1][2], accs[2 * ks + 1][3], ph[3], pl[3]);
#pragma unroll
            for (int np = 0; np < 4; np++) {
                uint32_t bh4[4], bl4[4];
                ldsm4t(bh4, vh_lm + ks * 2304 + np * 32);
                ldsm4t(bl4, vl_lm + ks * 2304 + np * 32);
                mma_bf16(acco[2 * np], ph, bh4);
                mma_bf16(acco[2 * np], pl, bh4);
                mma_bf16(acco[2 * np], ph, bl4);
                mma_bf16(acco[2 * np + 1], ph, bh4 + 2);
                mma_bf16(acco[2 * np + 1], pl, bh4 + 2);
                mma_bf16(acco[2 * np + 1], ph, bl4 + 2);
            }
        }
        __syncthreads();
    }

    // epilogue: normalize, split to bf16 hi/lo, store
    float inv0 = 1.0f / l0, inv1 = 1.0f / l1;
    int row0 = b * SS + q0 + wrow + g;
#pragma unroll
    for (int nt = 0; nt < 8; nt++) {
        int colh = h * 32 + nt * 4 + tg;
        uint32_t hhi, hlo;
        split2(acco[nt][0] * inv0, acco[nt][1] * inv0, hhi, hlo);
        outh[(size_t)row0 * 512 + colh] = hhi;
        outl[(size_t)row0 * 512 + colh] = hlo;
        split2(acco[nt][2] * inv1, acco[nt][3] * inv1, hhi, hlo);
        outh[(size_t)(row0 + 8) * 512 + colh] = hhi;
        outl[(size_t)(row0 + 8) * 512 + colh] = hlo;
    }
}

// ---------------------------------------------------------------------------
extern "C" void kernel_launch(void* const* d_in, const int* in_sizes, int n_in,
                              void* d_out, int out_size)
{
    const float* x     = (const float*)d_in[0];
    const float* W_qkv = (const float*)d_in[1];
    const float* b_qkv = (const float*)d_in[2];
    const float* W_o   = (const float*)d_in[3];
    const float* b_o   = (const float*)d_in[4];
    float* out = (float*)d_out;

    uint32_t *xh, *xl, *wqh, *wql, *woh, *wol, *qkvh, *qkvl, *ah, *al;
    cudaGetSymbolAddress((void**)&xh, g_xh);     cudaGetSymbolAddress((void**)&xl, g_xl);
    cudaGetSymbolAddress((void**)&wqh, g_wqh);   cudaGetSymbolAddress((void**)&wql, g_wql);
    cudaGetSymbolAddress((void**)&woh, g_woh);   cudaGetSymbolAddress((void**)&wol, g_wol);
    cudaGetSymbolAddress((void**)&qkvh, g_qkvh); cudaGetSymbolAddress((void**)&qkvl, g_qkvl);
    cudaGetSymbolAddress((void**)&ah, g_ah);     cudaGetSymbolAddress((void**)&al, g_al);

    cudaFuncSetAttribute(gemm_bf16_kernel,
                         cudaFuncAttributeMaxDynamicSharedMemorySize, GEMM_SMEM);
    cudaFuncSetAttribute(attn_kernel,
                         cudaFuncAttributeMaxDynamicSharedMemorySize, ATTN_SMEM);

    // 0) split inputs to bf16 hi/lo
    split_kernel<<<NROWS * DD / 4 / 256, 256>>>(x, xh, xl, NROWS * DD / 4);
    split_kernel<<<E3 * DD / 4 / 256, 256>>>(W_qkv, wqh, wql, E3 * DD / 4);
    split_kernel<<<EE * EE / 4 / 256, 256>>>(W_o, woh, wol, EE * EE / 4);

    // 1) QKV projection -> packed bf16 hi/lo
    gemm_bf16_kernel<<<dim3(E3 / GBM, NROWS / GBM), 256, GEMM_SMEM>>>(
        xh, xl, wqh, wql, b_qkv, nullptr, qkvh, qkvl, DD, E3);

    // 2) Attention (reads/writes packed bf16 hi/lo)
    attn_kernel<<<dim3(SS / 128, HH, BB), 256, ATTN_SMEM>>>(qkvh, qkvl, ah, al);

    // 3) Output projection -> fp32 out
    gemm_bf16_kernel<<<dim3(EE / GBM, NROWS / GBM), 256, GEMM_SMEM>>>(
        ah, al, woh, wol, b_o, out, nullptr, nullptr, EE, EE);
}